// round 12
// baseline (speedup 1.0000x reference)
#include <cuda_runtime.h>

#define NN   4096
#define HH   128
#define CAP  192   // max degree capacity; Binomial(4096,0.02) max ~= 127

// Scratch (device globals: allocation-free per harness rules)
__device__ float4 g_edge[NN * CAP];   // (j_bits, decay, wc, pad) per edge
__device__ int    g_deg[NN];
__device__ float  g_h[NN * HH];
__device__ float  g_h2[NN * HH];

// ---- packed fp32x2 helpers (Blackwell FFMA2 / FADD2) ----
__device__ __forceinline__ unsigned long long fma2(
    unsigned long long a, unsigned long long b, unsigned long long c)
{
    unsigned long long d;
    asm("fma.rn.f32x2 %0, %1, %2, %3;" : "=l"(d) : "l"(a), "l"(b), "l"(c));
    return d;
}
__device__ __forceinline__ unsigned long long fadd2(
    unsigned long long a, unsigned long long b)
{
    unsigned long long d;
    asm("add.rn.f32x2 %0, %1, %2;" : "=l"(d) : "l"(a), "l"(b));
    return d;
}
__device__ __forceinline__ unsigned long long packdup(float w)
{
    unsigned long long d;
    asm("mov.b64 %0, {%1, %1};" : "=l"(d) : "f"(w));
    return d;
}
__device__ __forceinline__ void unpack2(unsigned long long v, float& lo, float& hi)
{
    asm("mov.b64 {%0, %1}, %2;" : "=f"(lo), "=f"(hi) : "l"(v));
}

// ---------------------------------------------------------------------------
// Build per-row edge list from adj (2% dense) with loop-invariant weights.
// One warp per row; float4 adj scan. Edge order within a row is a fixed
// permutation (summation order is irrelevant and deterministic).
// ---------------------------------------------------------------------------
__global__ __launch_bounds__(256) void build_edges_kernel(
    const float* __restrict__ adj, const float* __restrict__ dist)
{
    int row  = blockIdx.x * 8 + (threadIdx.x >> 5);
    int lane = threadIdx.x & 31;
    if (row >= NN) return;
    const float4* arowv = (const float4*)(adj + (long)row * NN);  // 1024 float4
    const float*  drow  = dist + (long)row * NN;
    unsigned lt = (1u << lane) - 1u;
    int base = 0;
    for (int it = 0; it < 1024; it += 64) {
        float4 a = arowv[it + lane];
        float4 b = arowv[it + 32 + lane];
        unsigned m0 = __ballot_sync(0xffffffffu, a.x != 0.0f);
        unsigned m1 = __ballot_sync(0xffffffffu, a.y != 0.0f);
        unsigned m2 = __ballot_sync(0xffffffffu, a.z != 0.0f);
        unsigned m3 = __ballot_sync(0xffffffffu, a.w != 0.0f);
        unsigned n0 = __ballot_sync(0xffffffffu, b.x != 0.0f);
        unsigned n1 = __ballot_sync(0xffffffffu, b.y != 0.0f);
        unsigned n2 = __ballot_sync(0xffffffffu, b.z != 0.0f);
        unsigned n3 = __ballot_sync(0xffffffffu, b.w != 0.0f);
#pragma unroll
        for (int q = 0; q < 8; q++) {
            unsigned mask;
            float av;
            int col;
            switch (q) {
                case 0: mask = m0; av = a.x; col = (it + lane) * 4 + 0; break;
                case 1: mask = m1; av = a.y; col = (it + lane) * 4 + 1; break;
                case 2: mask = m2; av = a.z; col = (it + lane) * 4 + 2; break;
                case 3: mask = m3; av = a.w; col = (it + lane) * 4 + 3; break;
                case 4: mask = n0; av = b.x; col = (it + 32 + lane) * 4 + 0; break;
                case 5: mask = n1; av = b.y; col = (it + 32 + lane) * 4 + 1; break;
                case 6: mask = n2; av = b.z; col = (it + 32 + lane) * 4 + 2; break;
                default: mask = n3; av = b.w; col = (it + 32 + lane) * 4 + 3; break;
            }
            if (av != 0.0f) {
                int pos = base + __popc(mask & lt);
                if (pos < CAP) {
                    float d     = drow[col];
                    float decay = __expf(d * (-1.0f / 3.0f));
                    float r     = fmaxf(d, 1e-6f);
                    float inv   = 3.5f / r;
                    float i2    = inv * inv;
                    float i6    = i2 * i2 * i2;
                    float wc    = 0.04f * (i6 * i6 - i6);
                    g_edge[row * CAP + pos] =
                        make_float4(__int_as_float(col), decay, wc, 0.0f);
                }
            }
            base += __popc(mask);
        }
    }
    if (lane == 0) g_deg[row] = (base < CAP) ? base : CAP;
}

// ---------------------------------------------------------------------------
// h = x @ W_in + b_in  (4096x64 @ 64x128); 4 rows/block, grid 1024.
// ---------------------------------------------------------------------------
__global__ __launch_bounds__(128) void in_proj_kernel(
    const float* __restrict__ x, const float* __restrict__ W,
    const float* __restrict__ b)
{
    __shared__ __align__(16) float s_xT[64 * 4];   // [k][r]
    int c  = threadIdx.x;
    int r0 = blockIdx.x * 4;
    for (int i = threadIdx.x; i < 4 * 64; i += 128) {
        int r = i >> 6, k = i & 63;
        s_xT[k * 4 + r] = x[(long)(r0 + r) * 64 + k];
    }
    __syncthreads();

    typedef unsigned long long u64;
    u64 p01 = 0ull, p23 = 0ull;
    const float* wcol = W + c;
#pragma unroll 8
    for (int k = 0; k < 64; k++) {
        u64 ww = packdup(wcol[k * HH]);
        ulonglong2 av = *(const ulonglong2*)&s_xT[k * 4];
        p01 = fma2(av.x, ww, p01);
        p23 = fma2(av.y, ww, p23);
    }
    float h0, h1, h2, h3;
    unpack2(p01, h0, h1);
    unpack2(p23, h2, h3);
    float bias = b[c];
    g_h[(long)(r0 + 0) * HH + c] = h0 + bias;
    g_h[(long)(r0 + 1) * HH + c] = h1 + bias;
    g_h[(long)(r0 + 2) * HH + c] = h2 + bias;
    g_h[(long)(r0 + 3) * HH + c] = h3 + bias;
}

// ---------------------------------------------------------------------------
// Fused step: msg + mlp1 + mlp2 + residual + LN for 8 rows, 512 threads.
// src = h of previous step (read-only everywhere), dst = new h / final out.
// msg: 2 warps per row, 4-edge groups, shfl-reduced dots.
// update: thread = (c2 = tid&63 owning cols {c2, c2+64}, q = tid>>6 k-eighth);
// two-phase smem reduction of packed f32x2 partials.
// ---------------------------------------------------------------------------
__global__ __launch_bounds__(512) void step_kernel(
    const float* __restrict__ src, float* __restrict__ dst,
    const float* __restrict__ W1, const float* __restrict__ b1,
    const float* __restrict__ W2, const float* __restrict__ b2,
    const float* __restrict__ gamma, const float* __restrict__ beta)
{
    typedef unsigned long long u64;
    __shared__ __align__(16) float s_catT[256 * 8];      // [k][r] (8 KB)
    __shared__ __align__(16) float s_tT[128 * 8];        // [k][r] (4 KB)
    __shared__ __align__(16) u64   s_spill[4][64][8];    // (16 KB)
    __shared__ float s_mp[8][132];                       // p=1 msg partials
    __shared__ float s_y[8][132];
    int tid = threadIdx.x;
    int r0  = blockIdx.x * 8;

    // ---- stage h (transposed) ----
    for (int i = tid; i < 8 * 128; i += 512) {
        int r = i >> 7, k = i & 127;
        s_catT[k * 8 + r] = src[(long)(r0 + r) * HH + k];
    }

    // ---- msg phase: 2 warps per row ----
    int wid  = tid >> 5;
    int lane = tid & 31;
    int rloc = wid & 7;           // local row 0..7
    int p    = wid >> 3;          // warp pair index 0/1
    int row  = r0 + rloc;
    float4 hi4 = *(const float4*)&src[(long)row * HH + lane * 4];
    int deg = g_deg[row];
    const float4* ebase = &g_edge[row * CAP];
    float4 acc = make_float4(0.f, 0.f, 0.f, 0.f);

    for (int e0 = p * 4; e0 < deg; e0 += 8) {
        float4 em[4], hj[4];
#pragma unroll
        for (int qq = 0; qq < 4; qq++) {
            bool v = (e0 + qq) < deg;
            em[qq] = v ? ebase[e0 + qq] : make_float4(0.f, 0.f, 0.f, 0.f);
            int j = v ? __float_as_int(em[qq].x) : 0;
            hj[qq] = *(const float4*)&src[(long)j * HH + lane * 4];
        }
        float d[4];
#pragma unroll
        for (int qq = 0; qq < 4; qq++)
            d[qq] = hi4.x * hj[qq].x + hi4.y * hj[qq].y
                  + hi4.z * hj[qq].z + hi4.w * hj[qq].w;
#pragma unroll
        for (int o = 16; o > 0; o >>= 1) {
#pragma unroll
            for (int qq = 0; qq < 4; qq++)
                d[qq] += __shfl_xor_sync(0xffffffffu, d[qq], o);
        }
#pragma unroll
        for (int qq = 0; qq < 4; qq++) {
            float cf = fmaf(em[qq].y, fmaxf(d[qq], 0.0f), em[qq].z);
            acc.x = fmaf(cf, hj[qq].x, acc.x);
            acc.y = fmaf(cf, hj[qq].y, acc.y);
            acc.z = fmaf(cf, hj[qq].z, acc.z);
            acc.w = fmaf(cf, hj[qq].w, acc.w);
        }
    }
    if (p == 1) *(float4*)&s_mp[rloc][lane * 4] = acc;
    __syncthreads();
    if (p == 0) {
        float4 o4 = *(const float4*)&s_mp[rloc][lane * 4];
        acc.x += o4.x; acc.y += o4.y; acc.z += o4.z; acc.w += o4.w;
        *(float4*)&s_mp[rloc][lane * 4] = acc;
    }
    __syncthreads();
    // transpose m into s_catT k-range [128,256)
    for (int i = tid; i < 8 * 128; i += 512) {
        int r = i >> 7, k = i & 127;
        s_catT[(128 + k) * 8 + r] = s_mp[r][k];
    }
    __syncthreads();

    // ---- update phase ----
    int c2 = tid & 63;           // owns cols c2 and c2+64
    int q  = tid >> 6;           // 0..7 k-eighth

    u64 A0 = 0, A1 = 0, A2 = 0, A3 = 0;   // col c2, rows 0-7 packed
    u64 B0 = 0, B1 = 0, B2 = 0, B3 = 0;   // col c2+64
    {
        const float* w1a = W1 + (q * 32) * HH + c2;
        const float* w1b = w1a + 64;
        const float* base = &s_catT[(q * 32) * 8];
#pragma unroll 8
        for (int k = 0; k < 32; k++) {
            ulonglong2 x01 = *(const ulonglong2*)(base + k * 8);
            ulonglong2 x23 = *(const ulonglong2*)(base + k * 8 + 4);
            u64 wa = packdup(w1a[k * HH]);
            u64 wb = packdup(w1b[k * HH]);
            A0 = fma2(x01.x, wa, A0); A1 = fma2(x01.y, wa, A1);
            A2 = fma2(x23.x, wa, A2); A3 = fma2(x23.y, wa, A3);
            B0 = fma2(x01.x, wb, B0); B1 = fma2(x01.y, wb, B1);
            B2 = fma2(x23.x, wb, B2); B3 = fma2(x23.y, wb, B3);
        }
    }
    // two-phase reduction: q4-7 spill; q0-3 add; q1-3 spill; q0 final
    if (q >= 4) {
        u64* sp = s_spill[q - 4][c2];
        sp[0] = A0; sp[1] = A1; sp[2] = A2; sp[3] = A3;
        sp[4] = B0; sp[5] = B1; sp[6] = B2; sp[7] = B3;
    }
    __syncthreads();
    if (q < 4) {
        const u64* sp = s_spill[q][c2];
        A0 = fadd2(A0, sp[0]); A1 = fadd2(A1, sp[1]);
        A2 = fadd2(A2, sp[2]); A3 = fadd2(A3, sp[3]);
        B0 = fadd2(B0, sp[4]); B1 = fadd2(B1, sp[5]);
        B2 = fadd2(B2, sp[6]); B3 = fadd2(B3, sp[7]);
    }
    __syncthreads();
    if (q >= 1 && q < 4) {
        u64* sp = s_spill[q - 1][c2];
        sp[0] = A0; sp[1] = A1; sp[2] = A2; sp[3] = A3;
        sp[4] = B0; sp[5] = B1; sp[6] = B2; sp[7] = B3;
    }
    __syncthreads();
    if (q == 0) {
#pragma unroll
        for (int s = 0; s < 3; s++) {
            const u64* sp = s_spill[s][c2];
            A0 = fadd2(A0, sp[0]); A1 = fadd2(A1, sp[1]);
            A2 = fadd2(A2, sp[2]); A3 = fadd2(A3, sp[3]);
            B0 = fadd2(B0, sp[4]); B1 = fadd2(B1, sp[5]);
            B2 = fadd2(B2, sp[6]); B3 = fadd2(B3, sp[7]);
        }
        float ta[8], tb[8];
        unpack2(A0, ta[0], ta[1]); unpack2(A1, ta[2], ta[3]);
        unpack2(A2, ta[4], ta[5]); unpack2(A3, ta[6], ta[7]);
        unpack2(B0, tb[0], tb[1]); unpack2(B1, tb[2], tb[3]);
        unpack2(B2, tb[4], tb[5]); unpack2(B3, tb[6], tb[7]);
        float ba = b1[c2], bb = b1[c2 + 64];
        *(float4*)&s_tT[c2 * 8] = make_float4(
            fmaxf(ta[0] + ba, 0.0f), fmaxf(ta[1] + ba, 0.0f),
            fmaxf(ta[2] + ba, 0.0f), fmaxf(ta[3] + ba, 0.0f));
        *(float4*)&s_tT[c2 * 8 + 4] = make_float4(
            fmaxf(ta[4] + ba, 0.0f), fmaxf(ta[5] + ba, 0.0f),
            fmaxf(ta[6] + ba, 0.0f), fmaxf(ta[7] + ba, 0.0f));
        *(float4*)&s_tT[(c2 + 64) * 8] = make_float4(
            fmaxf(tb[0] + bb, 0.0f), fmaxf(tb[1] + bb, 0.0f),
            fmaxf(tb[2] + bb, 0.0f), fmaxf(tb[3] + bb, 0.0f));
        *(float4*)&s_tT[(c2 + 64) * 8 + 4] = make_float4(
            fmaxf(tb[4] + bb, 0.0f), fmaxf(tb[5] + bb, 0.0f),
            fmaxf(tb[6] + bb, 0.0f), fmaxf(tb[7] + bb, 0.0f));
    }
    __syncthreads();

    // ---- mlp2: delta = t @ W2 + b2 ----
    A0 = 0; A1 = 0; A2 = 0; A3 = 0;
    B0 = 0; B1 = 0; B2 = 0; B3 = 0;
    {
        const float* w2a = W2 + (q * 16) * HH + c2;
        const float* w2b = w2a + 64;
        const float* base = &s_tT[(q * 16) * 8];
#pragma unroll 8
        for (int k = 0; k < 16; k++) {
            ulonglong2 x01 = *(const ulonglong2*)(base + k * 8);
            ulonglong2 x23 = *(const ulonglong2*)(base + k * 8 + 4);
            u64 wa = packdup(w2a[k * HH]);
            u64 wb = packdup(w2b[k * HH]);
            A0 = fma2(x01.x, wa, A0); A1 = fma2(x01.y, wa, A1);
            A2 = fma2(x23.x, wa, A2); A3 = fma2(x23.y, wa, A3);
            B0 = fma2(x01.x, wb, B0); B1 = fma2(x01.y, wb, B1);
            B2 = fma2(x23.x, wb, B2); B3 = fma2(x23.y, wb, B3);
        }
    }
    if (q >= 4) {
        u64* sp = s_spill[q - 4][c2];
        sp[0] = A0; sp[1] = A1; sp[2] = A2; sp[3] = A3;
        sp[4] = B0; sp[5] = B1; sp[6] = B2; sp[7] = B3;
    }
    __syncthreads();
    if (q < 4) {
        const u64* sp = s_spill[q][c2];
        A0 = fadd2(A0, sp[0]); A1 = fadd2(A1, sp[1]);
        A2 = fadd2(A2, sp[2]); A3 = fadd2(A3, sp[3]);
        B0 = fadd2(B0, sp[4]); B1 = fadd2(B1, sp[5]);
        B2 = fadd2(B2, sp[6]); B3 = fadd2(B3, sp[7]);
    }
    __syncthreads();
    if (q >= 1 && q < 4) {
        u64* sp = s_spill[q - 1][c2];
        sp[0] = A0; sp[1] = A1; sp[2] = A2; sp[3] = A3;
        sp[4] = B0; sp[5] = B1; sp[6] = B2; sp[7] = B3;
    }
    __syncthreads();
    if (q == 0) {
#pragma unroll
        for (int s = 0; s < 3; s++) {
            const u64* sp = s_spill[s][c2];
            A0 = fadd2(A0, sp[0]); A1 = fadd2(A1, sp[1]);
            A2 = fadd2(A2, sp[2]); A3 = fadd2(A3, sp[3]);
            B0 = fadd2(B0, sp[4]); B1 = fadd2(B1, sp[5]);
            B2 = fadd2(B2, sp[6]); B3 = fadd2(B3, sp[7]);
        }
        float da[8], db[8];
        unpack2(A0, da[0], da[1]); unpack2(A1, da[2], da[3]);
        unpack2(A2, da[4], da[5]); unpack2(A3, da[6], da[7]);
        unpack2(B0, db[0], db[1]); unpack2(B1, db[2], db[3]);
        unpack2(B2, db[4], db[5]); unpack2(B3, db[6], db[7]);
        float ba = b2[c2], bb = b2[c2 + 64];
#pragma unroll
        for (int r = 0; r < 8; r++) {
            s_y[r][c2]      = s_catT[c2 * 8 + r]        + da[r] + ba;
            s_y[r][c2 + 64] = s_catT[(c2 + 64) * 8 + r] + db[r] + bb;
        }
    }
    __syncthreads();

    // ---- layernorm: warps 0-7 handle rows 0-7 ----
    if (wid < 8) {
        float4 gm = *(const float4*)&gamma[lane * 4];
        float4 bt = *(const float4*)&beta[lane * 4];
        float4 yv = *(const float4*)&s_y[wid][lane * 4];
        float s = yv.x + yv.y + yv.z + yv.w;
#pragma unroll
        for (int o = 16; o > 0; o >>= 1)
            s += __shfl_xor_sync(0xffffffffu, s, o);
        float mu = s * (1.0f / 128.0f);
        float dx = yv.x - mu, dy = yv.y - mu, dz = yv.z - mu, dw = yv.w - mu;
        float sq = dx * dx + dy * dy + dz * dz + dw * dw;
#pragma unroll
        for (int o = 16; o > 0; o >>= 1)
            sq += __shfl_xor_sync(0xffffffffu, sq, o);
        float rs = rsqrtf(sq * (1.0f / 128.0f) + 1e-5f);
        float4 o4;
        o4.x = dx * rs * gm.x + bt.x;
        o4.y = dy * rs * gm.y + bt.y;
        o4.z = dz * rs * gm.z + bt.z;
        o4.w = dw * rs * gm.w + bt.w;
        *(float4*)&dst[(long)(r0 + wid) * HH + lane * 4] = o4;
    }
}

// ---------------------------------------------------------------------------
extern "C" void kernel_launch(void* const* d_in, const int* in_sizes, int n_in,
                              void* d_out, int out_size)
{
    const float* x     = (const float*)d_in[0];
    const float* adj   = (const float*)d_in[1];
    const float* dist  = (const float*)d_in[2];
    const float* W_in  = (const float*)d_in[3];
    const float* b_in  = (const float*)d_in[4];
    // d_in[5] = W_msg, d_in[6] = b_msg : dead code in the reference
    const float* W_u1  = (const float*)d_in[7];
    const float* b_u1  = (const float*)d_in[8];
    const float* W_u2  = (const float*)d_in[9];
    const float* b_u2  = (const float*)d_in[10];
    const float* gamma = (const float*)d_in[11];
    const float* beta  = (const float*)d_in[12];
    float* out = (float*)d_out;

    float* h_ptr = nullptr;
    cudaGetSymbolAddress((void**)&h_ptr, g_h);
    float* h2_ptr = nullptr;
    cudaGetSymbolAddress((void**)&h2_ptr, g_h2);

    build_edges_kernel<<<NN / 8, 256>>>(adj, dist);
    in_proj_kernel<<<NN / 4, 128>>>(x, W_in, b_in);
    // step 0: g_h -> g_h2 ; step 1: g_h2 -> g_h ; step 2: g_h -> out
    step_kernel<<<NN / 8, 512>>>(h_ptr, h2_ptr, W_u1, b_u1, W_u2, b_u2, gamma, beta);
    step_kernel<<<NN / 8, 512>>>(h2_ptr, h_ptr, W_u1, b_u1, W_u2, b_u2, gamma, beta);
    step_kernel<<<NN / 8, 512>>>(h_ptr, out,    W_u1, b_u1, W_u2, b_u2, gamma, beta);
}

// round 13
// speedup vs baseline: 1.0522x; 1.0522x over previous
#include <cuda_runtime.h>

#define NN   4096
#define HH   128
#define CAP  192   // max degree capacity; Binomial(4096,0.02) max ~= 127

// Scratch (device globals: allocation-free per harness rules)
__device__ float4 g_edge[NN * CAP];   // (j_bits, decay, wc, pad) per edge
__device__ int    g_deg[NN];
__device__ float  g_h[NN * HH];
__device__ float  g_m[NN * HH];

// ---- packed fp32x2 helpers (Blackwell FFMA2 / FADD2) ----
__device__ __forceinline__ unsigned long long fma2(
    unsigned long long a, unsigned long long b, unsigned long long c)
{
    unsigned long long d;
    asm("fma.rn.f32x2 %0, %1, %2, %3;" : "=l"(d) : "l"(a), "l"(b), "l"(c));
    return d;
}
__device__ __forceinline__ unsigned long long fadd2(
    unsigned long long a, unsigned long long b)
{
    unsigned long long d;
    asm("add.rn.f32x2 %0, %1, %2;" : "=l"(d) : "l"(a), "l"(b));
    return d;
}
__device__ __forceinline__ unsigned long long packdup(float w)
{
    unsigned long long d;
    asm("mov.b64 %0, {%1, %1};" : "=l"(d) : "f"(w));
    return d;
}
__device__ __forceinline__ void unpack2(unsigned long long v, float& lo, float& hi)
{
    asm("mov.b64 {%0, %1}, %2;" : "=f"(lo), "=f"(hi) : "l"(v));
}

// ---------------------------------------------------------------------------
// Build per-row edge list from adj (2% dense) with loop-invariant weights.
// One warp per row; float4 adj scan. Edge order within a row is a fixed
// permutation (summation order is irrelevant and deterministic).
// ---------------------------------------------------------------------------
__global__ __launch_bounds__(256) void build_edges_kernel(
    const float* __restrict__ adj, const float* __restrict__ dist)
{
    int row  = blockIdx.x * 8 + (threadIdx.x >> 5);
    int lane = threadIdx.x & 31;
    if (row >= NN) return;
    const float4* arowv = (const float4*)(adj + (long)row * NN);  // 1024 float4
    const float*  drow  = dist + (long)row * NN;
    unsigned lt = (1u << lane) - 1u;
    int base = 0;
    for (int it = 0; it < 1024; it += 64) {
        float4 a = arowv[it + lane];
        float4 b = arowv[it + 32 + lane];
        unsigned m0 = __ballot_sync(0xffffffffu, a.x != 0.0f);
        unsigned m1 = __ballot_sync(0xffffffffu, a.y != 0.0f);
        unsigned m2 = __ballot_sync(0xffffffffu, a.z != 0.0f);
        unsigned m3 = __ballot_sync(0xffffffffu, a.w != 0.0f);
        unsigned n0 = __ballot_sync(0xffffffffu, b.x != 0.0f);
        unsigned n1 = __ballot_sync(0xffffffffu, b.y != 0.0f);
        unsigned n2 = __ballot_sync(0xffffffffu, b.z != 0.0f);
        unsigned n3 = __ballot_sync(0xffffffffu, b.w != 0.0f);
#pragma unroll
        for (int q = 0; q < 8; q++) {
            unsigned mask;
            float av;
            int col;
            switch (q) {
                case 0: mask = m0; av = a.x; col = (it + lane) * 4 + 0; break;
                case 1: mask = m1; av = a.y; col = (it + lane) * 4 + 1; break;
                case 2: mask = m2; av = a.z; col = (it + lane) * 4 + 2; break;
                case 3: mask = m3; av = a.w; col = (it + lane) * 4 + 3; break;
                case 4: mask = n0; av = b.x; col = (it + 32 + lane) * 4 + 0; break;
                case 5: mask = n1; av = b.y; col = (it + 32 + lane) * 4 + 1; break;
                case 6: mask = n2; av = b.z; col = (it + 32 + lane) * 4 + 2; break;
                default: mask = n3; av = b.w; col = (it + 32 + lane) * 4 + 3; break;
            }
            if (av != 0.0f) {
                int pos = base + __popc(mask & lt);
                if (pos < CAP) {
                    float d     = drow[col];
                    float decay = __expf(d * (-1.0f / 3.0f));
                    float r     = fmaxf(d, 1e-6f);
                    float inv   = 3.5f / r;
                    float i2    = inv * inv;
                    float i6    = i2 * i2 * i2;
                    float wc    = 0.04f * (i6 * i6 - i6);
                    g_edge[row * CAP + pos] =
                        make_float4(__int_as_float(col), decay, wc, 0.0f);
                }
            }
            base += __popc(mask);
        }
    }
    if (lane == 0) g_deg[row] = (base < CAP) ? base : CAP;
}

// ---------------------------------------------------------------------------
// h = x @ W_in + b_in  (4096x64 @ 64x128); 4 rows/block, grid 1024.
// ---------------------------------------------------------------------------
__global__ __launch_bounds__(128) void in_proj_kernel(
    const float* __restrict__ x, const float* __restrict__ W,
    const float* __restrict__ b)
{
    __shared__ __align__(16) float s_xT[64 * 4];   // [k][r]
    int c  = threadIdx.x;
    int r0 = blockIdx.x * 4;
    for (int i = threadIdx.x; i < 4 * 64; i += 128) {
        int r = i >> 6, k = i & 63;
        s_xT[k * 4 + r] = x[(long)(r0 + r) * 64 + k];
    }
    __syncthreads();

    typedef unsigned long long u64;
    u64 p01 = 0ull, p23 = 0ull;
    const float* wcol = W + c;
#pragma unroll 8
    for (int k = 0; k < 64; k++) {
        u64 ww = packdup(wcol[k * HH]);
        ulonglong2 av = *(const ulonglong2*)&s_xT[k * 4];
        p01 = fma2(av.x, ww, p01);
        p23 = fma2(av.y, ww, p23);
    }
    float h0, h1, h2, h3;
    unpack2(p01, h0, h1);
    unpack2(p23, h2, h3);
    float bias = b[c];
    g_h[(long)(r0 + 0) * HH + c] = h0 + bias;
    g_h[(long)(r0 + 1) * HH + c] = h1 + bias;
    g_h[(long)(r0 + 2) * HH + c] = h2 + bias;
    g_h[(long)(r0 + 3) * HH + c] = h3 + bias;
}

// ---------------------------------------------------------------------------
// m_i = sum_{j in N(i)} (decay_ij * relu(<h_i, h_j>) + wc_ij) * h_j
// One block (4 warps) per row; each warp processes 4 edges per iteration so
// four shfl-reduce chains interleave.
// ---------------------------------------------------------------------------
__global__ __launch_bounds__(128) void msg_kernel()
{
    __shared__ float s_hi[HH];
    __shared__ float s_m[4 * HH];
    int row  = blockIdx.x;
    int tid  = threadIdx.x;
    int wid  = tid >> 5;
    int lane = tid & 31;

    s_hi[tid] = g_h[(long)row * HH + tid];
    __syncthreads();
    float4 hi4 = *(const float4*)&s_hi[lane * 4];

    int deg = g_deg[row];
    const float4* ebase = &g_edge[row * CAP];
    float4 acc = make_float4(0.f, 0.f, 0.f, 0.f);

    for (int e0 = wid * 4; e0 < deg; e0 += 16) {
        float4 em[4], hj[4];
#pragma unroll
        for (int q = 0; q < 4; q++) {
            bool v = (e0 + q) < deg;
            em[q] = v ? ebase[e0 + q] : make_float4(0.f, 0.f, 0.f, 0.f);
            int j = v ? __float_as_int(em[q].x) : 0;
            hj[q] = *(const float4*)&g_h[(long)j * HH + lane * 4];
        }
        float d[4];
#pragma unroll
        for (int q = 0; q < 4; q++)
            d[q] = hi4.x * hj[q].x + hi4.y * hj[q].y
                 + hi4.z * hj[q].z + hi4.w * hj[q].w;
#pragma unroll
        for (int o = 16; o > 0; o >>= 1) {
#pragma unroll
            for (int q = 0; q < 4; q++)
                d[q] += __shfl_xor_sync(0xffffffffu, d[q], o);
        }
#pragma unroll
        for (int q = 0; q < 4; q++) {
            float cf = fmaf(em[q].y, fmaxf(d[q], 0.0f), em[q].z);  // 0 if invalid
            acc.x = fmaf(cf, hj[q].x, acc.x);
            acc.y = fmaf(cf, hj[q].y, acc.y);
            acc.z = fmaf(cf, hj[q].z, acc.z);
            acc.w = fmaf(cf, hj[q].w, acc.w);
        }
    }
    *(float4*)&s_m[wid * HH + lane * 4] = acc;
    __syncthreads();
    g_m[(long)row * HH + tid] =
        s_m[tid] + s_m[HH + tid] + s_m[2 * HH + tid] + s_m[3 * HH + tid];
}

// ---------------------------------------------------------------------------
// Fused update: t = relu([h|m]@W1+b1); delta = t@W2+b2; out = LN(h+delta)
// 8 rows/block, 512 threads, grid 512. Thread = (c2 = tid&63 owning cols
// {c2, c2+64}, q = tid>>6 k-eighth). Each broadcast-LDS activation feeds 2
// columns -> LDS.128 wavefronts per MAC halved vs 1-col layout; weight LDGs
// per block unchanged (each W element read exactly once per block).
// Two-phase smem reduction of packed f32x2 partials.
// ---------------------------------------------------------------------------
__global__ __launch_bounds__(512) void update_kernel(
    const float* __restrict__ W1, const float* __restrict__ b1,
    const float* __restrict__ W2, const float* __restrict__ b2,
    const float* __restrict__ gamma, const float* __restrict__ beta,
    float* __restrict__ out)
{
    typedef unsigned long long u64;
    __shared__ __align__(16) float s_catT[256 * 8];      // [k][r] (8 KB)
    __shared__ __align__(16) float s_tT[128 * 8];        // [k][r] (4 KB)
    __shared__ __align__(16) u64   s_spill[4][64][8];    // (16 KB)
    __shared__ float s_y[8][132];
    int tid = threadIdx.x;
    int r0  = blockIdx.x * 8;
    int c2  = tid & 63;           // owns cols c2 and c2+64
    int q   = tid >> 6;           // 0..7 k-eighth

    for (int i = tid; i < 8 * 128; i += 512) {
        int r = i >> 7, k = i & 127;
        s_catT[k * 8 + r]         = g_h[(long)(r0 + r) * HH + k];
        s_catT[(128 + k) * 8 + r] = g_m[(long)(r0 + r) * HH + k];
    }
    __syncthreads();

    // ---- mlp1: t = relu(cat @ W1 + b1) ----
    u64 A0 = 0, A1 = 0, A2 = 0, A3 = 0;   // col c2, rows 0-7 packed
    u64 B0 = 0, B1 = 0, B2 = 0, B3 = 0;   // col c2+64
    {
        const float* w1a = W1 + (q * 32) * HH + c2;
        const float* w1b = w1a + 64;
        const float* base = &s_catT[(q * 32) * 8];
#pragma unroll 8
        for (int k = 0; k < 32; k++) {
            ulonglong2 x01 = *(const ulonglong2*)(base + k * 8);
            ulonglong2 x23 = *(const ulonglong2*)(base + k * 8 + 4);
            u64 wa = packdup(w1a[k * HH]);
            u64 wb = packdup(w1b[k * HH]);
            A0 = fma2(x01.x, wa, A0); A1 = fma2(x01.y, wa, A1);
            A2 = fma2(x23.x, wa, A2); A3 = fma2(x23.y, wa, A3);
            B0 = fma2(x01.x, wb, B0); B1 = fma2(x01.y, wb, B1);
            B2 = fma2(x23.x, wb, B2); B3 = fma2(x23.y, wb, B3);
        }
    }
    // two-phase reduction: q4-7 spill; q0-3 add; q1-3 spill; q0 final
    if (q >= 4) {
        u64* sp = s_spill[q - 4][c2];
        sp[0] = A0; sp[1] = A1; sp[2] = A2; sp[3] = A3;
        sp[4] = B0; sp[5] = B1; sp[6] = B2; sp[7] = B3;
    }
    __syncthreads();
    if (q < 4) {
        const u64* sp = s_spill[q][c2];
        A0 = fadd2(A0, sp[0]); A1 = fadd2(A1, sp[1]);
        A2 = fadd2(A2, sp[2]); A3 = fadd2(A3, sp[3]);
        B0 = fadd2(B0, sp[4]); B1 = fadd2(B1, sp[5]);
        B2 = fadd2(B2, sp[6]); B3 = fadd2(B3, sp[7]);
    }
    __syncthreads();
    if (q >= 1 && q < 4) {
        u64* sp = s_spill[q - 1][c2];
        sp[0] = A0; sp[1] = A1; sp[2] = A2; sp[3] = A3;
        sp[4] = B0; sp[5] = B1; sp[6] = B2; sp[7] = B3;
    }
    __syncthreads();
    if (q == 0) {
#pragma unroll
        for (int s = 0; s < 3; s++) {
            const u64* sp = s_spill[s][c2];
            A0 = fadd2(A0, sp[0]); A1 = fadd2(A1, sp[1]);
            A2 = fadd2(A2, sp[2]); A3 = fadd2(A3, sp[3]);
            B0 = fadd2(B0, sp[4]); B1 = fadd2(B1, sp[5]);
            B2 = fadd2(B2, sp[6]); B3 = fadd2(B3, sp[7]);
        }
        float ta[8], tb[8];
        unpack2(A0, ta[0], ta[1]); unpack2(A1, ta[2], ta[3]);
        unpack2(A2, ta[4], ta[5]); unpack2(A3, ta[6], ta[7]);
        unpack2(B0, tb[0], tb[1]); unpack2(B1, tb[2], tb[3]);
        unpack2(B2, tb[4], tb[5]); unpack2(B3, tb[6], tb[7]);
        float ba = b1[c2], bb = b1[c2 + 64];
        *(float4*)&s_tT[c2 * 8] = make_float4(
            fmaxf(ta[0] + ba, 0.0f), fmaxf(ta[1] + ba, 0.0f),
            fmaxf(ta[2] + ba, 0.0f), fmaxf(ta[3] + ba, 0.0f));
        *(float4*)&s_tT[c2 * 8 + 4] = make_float4(
            fmaxf(ta[4] + ba, 0.0f), fmaxf(ta[5] + ba, 0.0f),
            fmaxf(ta[6] + ba, 0.0f), fmaxf(ta[7] + ba, 0.0f));
        *(float4*)&s_tT[(c2 + 64) * 8] = make_float4(
            fmaxf(tb[0] + bb, 0.0f), fmaxf(tb[1] + bb, 0.0f),
            fmaxf(tb[2] + bb, 0.0f), fmaxf(tb[3] + bb, 0.0f));
        *(float4*)&s_tT[(c2 + 64) * 8 + 4] = make_float4(
            fmaxf(tb[4] + bb, 0.0f), fmaxf(tb[5] + bb, 0.0f),
            fmaxf(tb[6] + bb, 0.0f), fmaxf(tb[7] + bb, 0.0f));
    }
    __syncthreads();

    // ---- mlp2: delta = t @ W2 + b2 ----
    A0 = 0; A1 = 0; A2 = 0; A3 = 0;
    B0 = 0; B1 = 0; B2 = 0; B3 = 0;
    {
        const float* w2a = W2 + (q * 16) * HH + c2;
        const float* w2b = w2a + 64;
        const float* base = &s_tT[(q * 16) * 8];
#pragma unroll 8
        for (int k = 0; k < 16; k++) {
            ulonglong2 x01 = *(const ulonglong2*)(base + k * 8);
            ulonglong2 x23 = *(const ulonglong2*)(base + k * 8 + 4);
            u64 wa = packdup(w2a[k * HH]);
            u64 wb = packdup(w2b[k * HH]);
            A0 = fma2(x01.x, wa, A0); A1 = fma2(x01.y, wa, A1);
            A2 = fma2(x23.x, wa, A2); A3 = fma2(x23.y, wa, A3);
            B0 = fma2(x01.x, wb, B0); B1 = fma2(x01.y, wb, B1);
            B2 = fma2(x23.x, wb, B2); B3 = fma2(x23.y, wb, B3);
        }
    }
    if (q >= 4) {
        u64* sp = s_spill[q - 4][c2];
        sp[0] = A0; sp[1] = A1; sp[2] = A2; sp[3] = A3;
        sp[4] = B0; sp[5] = B1; sp[6] = B2; sp[7] = B3;
    }
    __syncthreads();
    if (q < 4) {
        const u64* sp = s_spill[q][c2];
        A0 = fadd2(A0, sp[0]); A1 = fadd2(A1, sp[1]);
        A2 = fadd2(A2, sp[2]); A3 = fadd2(A3, sp[3]);
        B0 = fadd2(B0, sp[4]); B1 = fadd2(B1, sp[5]);
        B2 = fadd2(B2, sp[6]); B3 = fadd2(B3, sp[7]);
    }
    __syncthreads();
    if (q >= 1 && q < 4) {
        u64* sp = s_spill[q - 1][c2];
        sp[0] = A0; sp[1] = A1; sp[2] = A2; sp[3] = A3;
        sp[4] = B0; sp[5] = B1; sp[6] = B2; sp[7] = B3;
    }
    __syncthreads();
    if (q == 0) {
#pragma unroll
        for (int s = 0; s < 3; s++) {
            const u64* sp = s_spill[s][c2];
            A0 = fadd2(A0, sp[0]); A1 = fadd2(A1, sp[1]);
            A2 = fadd2(A2, sp[2]); A3 = fadd2(A3, sp[3]);
            B0 = fadd2(B0, sp[4]); B1 = fadd2(B1, sp[5]);
            B2 = fadd2(B2, sp[6]); B3 = fadd2(B3, sp[7]);
        }
        float da[8], db[8];
        unpack2(A0, da[0], da[1]); unpack2(A1, da[2], da[3]);
        unpack2(A2, da[4], da[5]); unpack2(A3, da[6], da[7]);
        unpack2(B0, db[0], db[1]); unpack2(B1, db[2], db[3]);
        unpack2(B2, db[4], db[5]); unpack2(B3, db[6], db[7]);
        float ba = b2[c2], bb = b2[c2 + 64];
#pragma unroll
        for (int r = 0; r < 8; r++) {
            s_y[r][c2]      = s_catT[c2 * 8 + r]        + da[r] + ba;
            s_y[r][c2 + 64] = s_catT[(c2 + 64) * 8 + r] + db[r] + bb;
        }
    }
    __syncthreads();

    // ---- layernorm: warps 0-7 handle rows 0-7; lane owns 4 cols ----
    int wid  = tid >> 5;
    int lane = tid & 31;
    if (wid < 8) {
        float4 gm = *(const float4*)&gamma[lane * 4];
        float4 bt = *(const float4*)&beta[lane * 4];
        float4 yv = *(const float4*)&s_y[wid][lane * 4];
        float s = yv.x + yv.y + yv.z + yv.w;
#pragma unroll
        for (int o = 16; o > 0; o >>= 1)
            s += __shfl_xor_sync(0xffffffffu, s, o);
        float mu = s * (1.0f / 128.0f);
        float dx = yv.x - mu, dy = yv.y - mu, dz = yv.z - mu, dw = yv.w - mu;
        float sq = dx * dx + dy * dy + dz * dz + dw * dw;
#pragma unroll
        for (int o = 16; o > 0; o >>= 1)
            sq += __shfl_xor_sync(0xffffffffu, sq, o);
        float rs = rsqrtf(sq * (1.0f / 128.0f) + 1e-5f);
        float4 o4;
        o4.x = dx * rs * gm.x + bt.x;
        o4.y = dy * rs * gm.y + bt.y;
        o4.z = dz * rs * gm.z + bt.z;
        o4.w = dw * rs * gm.w + bt.w;
        *(float4*)&out[(long)(r0 + wid) * HH + lane * 4] = o4;
    }
}

// ---------------------------------------------------------------------------
extern "C" void kernel_launch(void* const* d_in, const int* in_sizes, int n_in,
                              void* d_out, int out_size)
{
    const float* x     = (const float*)d_in[0];
    const float* adj   = (const float*)d_in[1];
    const float* dist  = (const float*)d_in[2];
    const float* W_in  = (const float*)d_in[3];
    const float* b_in  = (const float*)d_in[4];
    // d_in[5] = W_msg, d_in[6] = b_msg : dead code in the reference
    const float* W_u1  = (const float*)d_in[7];
    const float* b_u1  = (const float*)d_in[8];
    const float* W_u2  = (const float*)d_in[9];
    const float* b_u2  = (const float*)d_in[10];
    const float* gamma = (const float*)d_in[11];
    const float* beta  = (const float*)d_in[12];
    float* out = (float*)d_out;

    float* h_ptr = nullptr;
    cudaGetSymbolAddress((void**)&h_ptr, g_h);

    build_edges_kernel<<<NN / 8, 256>>>(adj, dist);
    in_proj_kernel<<<NN / 4, 128>>>(x, W_in, b_in);
    for (int s = 0; s < 3; s++) {
        msg_kernel<<<NN, 128>>>();
        update_kernel<<<NN / 8, 512>>>(W_u1, b_u1, W_u2, b_u2, gamma, beta,
                                       (s == 2) ? out : h_ptr);
    }
}

// round 16
// speedup vs baseline: 1.1515x; 1.0944x over previous
#include <cuda_runtime.h>

#define NN   4096
#define HH   128
#define CAP  192   // max degree capacity; Binomial(4096,0.02) max ~= 127

// Scratch (device globals: allocation-free per harness rules)
__device__ float4 g_edge[NN * CAP];   // (j_bits, decay, wc, pad) per edge
__device__ int    g_deg[NN];
__device__ float  g_h[NN * HH];
__device__ float  g_m[NN * HH];
__device__ uint2  g_W1p[32 * 4 * 128];   // paired tf32 W1: [ks][tig][n] -> (k, k+4)
__device__ uint2  g_W2p[16 * 4 * 128];   // paired tf32 W2

// ---- packed fp32x2 helpers (Blackwell FFMA2) ----
__device__ __forceinline__ unsigned long long fma2(
    unsigned long long a, unsigned long long b, unsigned long long c)
{
    unsigned long long d;
    asm("fma.rn.f32x2 %0, %1, %2, %3;" : "=l"(d) : "l"(a), "l"(b), "l"(c));
    return d;
}
__device__ __forceinline__ unsigned long long packdup(float w)
{
    unsigned long long d;
    asm("mov.b64 %0, {%1, %1};" : "=l"(d) : "f"(w));
    return d;
}
__device__ __forceinline__ void unpack2(unsigned long long v, float& lo, float& hi)
{
    asm("mov.b64 {%0, %1}, %2;" : "=f"(lo), "=f"(hi) : "l"(v));
}
// ---- tf32 helpers ----
__device__ __forceinline__ unsigned f2tf32(float f)
{
    unsigned r;
    asm("cvt.rna.tf32.f32 %0, %1;" : "=r"(r) : "f"(f));
    return r;
}
__device__ __forceinline__ void mma_tf32(float* C,
    unsigned a0, unsigned a1, unsigned a2, unsigned a3,
    unsigned b0, unsigned b1)
{
    asm("mma.sync.aligned.m16n8k8.row.col.f32.tf32.tf32.f32 "
        "{%0,%1,%2,%3}, {%4,%5,%6,%7}, {%8,%9}, {%0,%1,%2,%3};"
        : "+f"(C[0]), "+f"(C[1]), "+f"(C[2]), "+f"(C[3])
        : "r"(a0), "r"(a1), "r"(a2), "r"(a3), "r"(b0), "r"(b1));
}

// ---------------------------------------------------------------------------
// Pack W1/W2 into tf32 pairs: g_Wp[(ks*4+tig)*128 + n] = (W[ks*8+tig][n],
// W[ks*8+tig+4][n]) so one LDG.64 yields a full mma B-fragment.
// ---------------------------------------------------------------------------
__global__ void prep_w_kernel(const float* __restrict__ W1,
                              const float* __restrict__ W2)
{
    int i = blockIdx.x * 256 + threadIdx.x;   // 0 .. 16383
    if (i < 32 * 4 * 128) {
        int n = i & 127, t = (i >> 7) & 3, ks = i >> 9;
        g_W1p[i] = make_uint2(f2tf32(W1[(ks * 8 + t) * 128 + n]),
                              f2tf32(W1[(ks * 8 + t + 4) * 128 + n]));
    }
    if (i < 16 * 4 * 128) {
        int n = i & 127, t = (i >> 7) & 3, ks = i >> 9;
        g_W2p[i] = make_uint2(f2tf32(W2[(ks * 8 + t) * 128 + n]),
                              f2tf32(W2[(ks * 8 + t + 4) * 128 + n]));
    }
}

// ---------------------------------------------------------------------------
// Build per-row edge list from adj (2% dense) with loop-invariant weights.
// ---------------------------------------------------------------------------
__global__ __launch_bounds__(256) void build_edges_kernel(
    const float* __restrict__ adj, const float* __restrict__ dist)
{
    int row  = blockIdx.x * 8 + (threadIdx.x >> 5);
    int lane = threadIdx.x & 31;
    if (row >= NN) return;
    const float4* arowv = (const float4*)(adj + (long)row * NN);  // 1024 float4
    const float*  drow  = dist + (long)row * NN;
    unsigned lt = (1u << lane) - 1u;
    int base = 0;
    for (int it = 0; it < 1024; it += 64) {
        float4 a = arowv[it + lane];
        float4 b = arowv[it + 32 + lane];
        unsigned m0 = __ballot_sync(0xffffffffu, a.x != 0.0f);
        unsigned m1 = __ballot_sync(0xffffffffu, a.y != 0.0f);
        unsigned m2 = __ballot_sync(0xffffffffu, a.z != 0.0f);
        unsigned m3 = __ballot_sync(0xffffffffu, a.w != 0.0f);
        unsigned n0 = __ballot_sync(0xffffffffu, b.x != 0.0f);
        unsigned n1 = __ballot_sync(0xffffffffu, b.y != 0.0f);
        unsigned n2 = __ballot_sync(0xffffffffu, b.z != 0.0f);
        unsigned n3 = __ballot_sync(0xffffffffu, b.w != 0.0f);
#pragma unroll
        for (int q = 0; q < 8; q++) {
            unsigned mask;
            float av;
            int col;
            switch (q) {
                case 0: mask = m0; av = a.x; col = (it + lane) * 4 + 0; break;
                case 1: mask = m1; av = a.y; col = (it + lane) * 4 + 1; break;
                case 2: mask = m2; av = a.z; col = (it + lane) * 4 + 2; break;
                case 3: mask = m3; av = a.w; col = (it + lane) * 4 + 3; break;
                case 4: mask = n0; av = b.x; col = (it + 32 + lane) * 4 + 0; break;
                case 5: mask = n1; av = b.y; col = (it + 32 + lane) * 4 + 1; break;
                case 6: mask = n2; av = b.z; col = (it + 32 + lane) * 4 + 2; break;
                default: mask = n3; av = b.w; col = (it + 32 + lane) * 4 + 3; break;
            }
            if (av != 0.0f) {
                int pos = base + __popc(mask & lt);
                if (pos < CAP) {
                    float d     = drow[col];
                    float decay = __expf(d * (-1.0f / 3.0f));
                    float r     = fmaxf(d, 1e-6f);
                    float inv   = 3.5f / r;
                    float i2    = inv * inv;
                    float i6    = i2 * i2 * i2;
                    float wc    = 0.04f * (i6 * i6 - i6);
                    g_edge[row * CAP + pos] =
                        make_float4(__int_as_float(col), decay, wc, 0.0f);
                }
            }
            base += __popc(mask);
        }
    }
    if (lane == 0) g_deg[row] = (base < CAP) ? base : CAP;
}

// ---------------------------------------------------------------------------
// h = x @ W_in + b_in  (4096x64 @ 64x128); 4 rows/block, grid 1024.
// ---------------------------------------------------------------------------
__global__ __launch_bounds__(128) void in_proj_kernel(
    const float* __restrict__ x, const float* __restrict__ W,
    const float* __restrict__ b)
{
    __shared__ __align__(16) float s_xT[64 * 4];   // [k][r]
    int c  = threadIdx.x;
    int r0 = blockIdx.x * 4;
    for (int i = threadIdx.x; i < 4 * 64; i += 128) {
        int r = i >> 6, k = i & 63;
        s_xT[k * 4 + r] = x[(long)(r0 + r) * 64 + k];
    }
    __syncthreads();

    typedef unsigned long long u64;
    u64 p01 = 0ull, p23 = 0ull;
    const float* wcol = W + c;
#pragma unroll 8
    for (int k = 0; k < 64; k++) {
        u64 ww = packdup(wcol[k * HH]);
        ulonglong2 av = *(const ulonglong2*)&s_xT[k * 4];
        p01 = fma2(av.x, ww, p01);
        p23 = fma2(av.y, ww, p23);
    }
    float h0, h1, h2, h3;
    unpack2(p01, h0, h1);
    unpack2(p23, h2, h3);
    float bias = b[c];
    g_h[(long)(r0 + 0) * HH + c] = h0 + bias;
    g_h[(long)(r0 + 1) * HH + c] = h1 + bias;
    g_h[(long)(r0 + 2) * HH + c] = h2 + bias;
    g_h[(long)(r0 + 3) * HH + c] = h3 + bias;
}

// ---------------------------------------------------------------------------
// m_i = sum_{j in N(i)} (decay_ij * relu(<h_i, h_j>) + wc_ij) * h_j
// One block (4 warps) per row; 4 edges per warp-iteration.
// ---------------------------------------------------------------------------
__global__ __launch_bounds__(128) void msg_kernel()
{
    __shared__ float s_hi[HH];
    __shared__ float s_m[4 * HH];
    int row  = blockIdx.x;
    int tid  = threadIdx.x;
    int wid  = tid >> 5;
    int lane = tid & 31;

    s_hi[tid] = g_h[(long)row * HH + tid];
    __syncthreads();
    float4 hi4 = *(const float4*)&s_hi[lane * 4];

    int deg = g_deg[row];
    const float4* ebase = &g_edge[row * CAP];
    float4 acc = make_float4(0.f, 0.f, 0.f, 0.f);

    for (int e0 = wid * 4; e0 < deg; e0 += 16) {
        float4 em[4], hj[4];
#pragma unroll
        for (int q = 0; q < 4; q++) {
            bool v = (e0 + q) < deg;
            em[q] = v ? ebase[e0 + q] : make_float4(0.f, 0.f, 0.f, 0.f);
            int j = v ? __float_as_int(em[q].x) : 0;
            hj[q] = *(const float4*)&g_h[(long)j * HH + lane * 4];
        }
        float d[4];
#pragma unroll
        for (int q = 0; q < 4; q++)
            d[q] = hi4.x * hj[q].x + hi4.y * hj[q].y
                 + hi4.z * hj[q].z + hi4.w * hj[q].w;
#pragma unroll
        for (int o = 16; o > 0; o >>= 1) {
#pragma unroll
            for (int q = 0; q < 4; q++)
                d[q] += __shfl_xor_sync(0xffffffffu, d[q], o);
        }
#pragma unroll
        for (int q = 0; q < 4; q++) {
            float cf = fmaf(em[q].y, fmaxf(d[q], 0.0f), em[q].z);  // 0 if invalid
            acc.x = fmaf(cf, hj[q].x, acc.x);
            acc.y = fmaf(cf, hj[q].y, acc.y);
            acc.z = fmaf(cf, hj[q].z, acc.z);
            acc.w = fmaf(cf, hj[q].w, acc.w);
        }
    }
    *(float4*)&s_m[wid * HH + lane * 4] = acc;
    __syncthreads();
    g_m[(long)row * HH + tid] =
        s_m[tid] + s_m[HH + tid] + s_m[2 * HH + tid] + s_m[3 * HH + tid];
}

// ---------------------------------------------------------------------------
// Tensor-core update: t = relu([h|m]@W1+b1); delta = t@W2+b2; out = LN(h+delta)
// 16 rows/block, 256 threads (8 warps), grid 256.
// mma.sync m16n8k8 tf32. Warp = (khalf = w>>2, nslice = (w&3)*32).
// khalf=1 partials reduced into khalf=0 via smem (exact fp32 adds).
// Residual + LN in exact fp32 (activations kept fp32 in smem; cvt at A-load).
// ---------------------------------------------------------------------------
__global__ __launch_bounds__(256) void update_tc_kernel(
    const float* __restrict__ b1, const float* __restrict__ b2,
    const float* __restrict__ gamma, const float* __restrict__ beta,
    float* __restrict__ out)
{
    __shared__ float s_cat[16][260];      // fp32 [row][k]: k<128 h, k>=128 m
    __shared__ float s_t[16][132];        // fp32 relu output
    __shared__ float s_red[4][32][16];    // khalf=1 fragment spills
    __shared__ float s_y[16][132];        // pre-LN rows
    int tid    = threadIdx.x;
    int warp   = tid >> 5;
    int lane   = tid & 31;
    int g      = lane >> 2;     // 0..7
    int tig    = lane & 3;      // 0..3
    int khalf  = warp >> 2;     // 0/1
    int wq     = warp & 3;      // n-slice index
    int nslice = wq * 32;
    int r0     = blockIdx.x * 16;

    for (int i = tid; i < 16 * 128; i += 256) {
        int r = i >> 7, k = i & 127;
        s_cat[r][k]       = g_h[(long)(r0 + r) * HH + k];
        s_cat[r][128 + k] = g_m[(long)(r0 + r) * HH + k];
    }
    __syncthreads();

    // ---- mlp1: C += cat @ W1 over this warp's k-half ----
    float C[4][4];
#pragma unroll
    for (int nt = 0; nt < 4; nt++)
#pragma unroll
        for (int j = 0; j < 4; j++) C[nt][j] = 0.0f;

    for (int ks = 0; ks < 16; ks++) {
        int ksg = khalf * 16 + ks;
        int k0  = ksg * 8;
        unsigned a0 = f2tf32(s_cat[g][k0 + tig]);
        unsigned a1 = f2tf32(s_cat[g + 8][k0 + tig]);
        unsigned a2 = f2tf32(s_cat[g][k0 + tig + 4]);
        unsigned a3 = f2tf32(s_cat[g + 8][k0 + tig + 4]);
        const uint2* wp = g_W1p + (ksg * 4 + tig) * 128 + nslice + g;
#pragma unroll
        for (int nt = 0; nt < 4; nt++) {
            uint2 b = wp[nt * 8];
            mma_tf32(C[nt], a0, a1, a2, a3, b.x, b.y);
        }
    }
    if (khalf == 1) {
        float4* dst = (float4*)&s_red[wq][lane][0];
#pragma unroll
        for (int nt = 0; nt < 4; nt++)
            dst[nt] = make_float4(C[nt][0], C[nt][1], C[nt][2], C[nt][3]);
    }
    __syncthreads();
    if (khalf == 0) {
        const float* sp = &s_red[wq][lane][0];
#pragma unroll
        for (int nt = 0; nt < 4; nt++) {
            int colb = nslice + nt * 8 + 2 * tig;
            float bi0 = b1[colb], bi1 = b1[colb + 1];
            s_t[g][colb]         = fmaxf(C[nt][0] + sp[nt * 4 + 0] + bi0, 0.0f);
            s_t[g][colb + 1]     = fmaxf(C[nt][1] + sp[nt * 4 + 1] + bi1, 0.0f);
            s_t[g + 8][colb]     = fmaxf(C[nt][2] + sp[nt * 4 + 2] + bi0, 0.0f);
            s_t[g + 8][colb + 1] = fmaxf(C[nt][3] + sp[nt * 4 + 3] + bi1, 0.0f);
        }
    }
    __syncthreads();

    // ---- mlp2: D += t @ W2 over this warp's k-half ----
#pragma unroll
    for (int nt = 0; nt < 4; nt++)
#pragma unroll
        for (int j = 0; j < 4; j++) C[nt][j] = 0.0f;

    for (int ks = 0; ks < 8; ks++) {
        int ksg = khalf * 8 + ks;
        int k0  = ksg * 8;
        unsigned a0 = f2tf32(s_t[g][k0 + tig]);
        unsigned a1 = f2tf32(s_t[g + 8][k0 + tig]);
        unsigned a2 = f2tf32(s_t[g][k0 + tig + 4]);
        unsigned a3 = f2tf32(s_t[g + 8][k0 + tig + 4]);
        const uint2* wp = g_W2p + (ksg * 4 + tig) * 128 + nslice + g;
#pragma unroll
        for (int nt = 0; nt < 4; nt++) {
            uint2 b = wp[nt * 8];
            mma_tf32(C[nt], a0, a1, a2, a3, b.x, b.y);
        }
    }
    if (khalf == 1) {
        float4* dst = (float4*)&s_red[wq][lane][0];
#pragma unroll
        for (int nt = 0; nt < 4; nt++)
            dst[nt] = make_float4(C[nt][0], C[nt][1], C[nt][2], C[nt][3]);
    }
    __syncthreads();
    if (khalf == 0) {
        const float* sp = &s_red[wq][lane][0];
#pragma unroll
        for (int nt = 0; nt < 4; nt++) {
            int colb = nslice + nt * 8 + 2 * tig;
            float bi0 = b2[colb], bi1 = b2[colb + 1];
            s_y[g][colb]         = s_cat[g][colb]         + C[nt][0] + sp[nt * 4 + 0] + bi0;
            s_y[g][colb + 1]     = s_cat[g][colb + 1]     + C[nt][1] + sp[nt * 4 + 1] + bi1;
            s_y[g + 8][colb]     = s_cat[g + 8][colb]     + C[nt][2] + sp[nt * 4 + 2] + bi0;
            s_y[g + 8][colb + 1] = s_cat[g + 8][colb + 1] + C[nt][3] + sp[nt * 4 + 3] + bi1;
        }
    }
    __syncthreads();

    // ---- layernorm: warp w handles rows w and w+8 ----
    float4 gm = *(const float4*)&gamma[lane * 4];
    float4 bt = *(const float4*)&beta[lane * 4];
#pragma unroll
    for (int rr = 0; rr < 2; rr++) {
        int r = warp + rr * 8;
        float4 yv = *(const float4*)&s_y[r][lane * 4];
        float s = yv.x + yv.y + yv.z + yv.w;
#pragma unroll
        for (int o = 16; o > 0; o >>= 1)
            s += __shfl_xor_sync(0xffffffffu, s, o);
        float mu = s * (1.0f / 128.0f);
        float dx = yv.x - mu, dy = yv.y - mu, dz = yv.z - mu, dw = yv.w - mu;
        float sq = dx * dx + dy * dy + dz * dz + dw * dw;
#pragma unroll
        for (int o = 16; o > 0; o >>= 1)
            sq += __shfl_xor_sync(0xffffffffu, sq, o);
        float rs = rsqrtf(sq * (1.0f / 128.0f) + 1e-5f);
        float4 o4;
        o4.x = dx * rs * gm.x + bt.x;
        o4.y = dy * rs * gm.y + bt.y;
        o4.z = dz * rs * gm.z + bt.z;
        o4.w = dw * rs * gm.w + bt.w;
        *(float4*)&out[(long)(r0 + r) * HH + lane * 4] = o4;
    }
}

// ---------------------------------------------------------------------------
extern "C" void kernel_launch(void* const* d_in, const int* in_sizes, int n_in,
                              void* d_out, int out_size)
{
    const float* x     = (const float*)d_in[0];
    const float* adj   = (const float*)d_in[1];
    const float* dist  = (const float*)d_in[2];
    const float* W_in  = (const float*)d_in[3];
    const float* b_in  = (const float*)d_in[4];
    // d_in[5] = W_msg, d_in[6] = b_msg : dead code in the reference
    const float* W_u1  = (const float*)d_in[7];
    const float* b_u1  = (const float*)d_in[8];
    const float* W_u2  = (const float*)d_in[9];
    const float* b_u2  = (const float*)d_in[10];
    const float* gamma = (const float*)d_in[11];
    const float* beta  = (const float*)d_in[12];
    float* out = (float*)d_out;

    float* h_ptr = nullptr;
    cudaGetSymbolAddress((void**)&h_ptr, g_h);

    prep_w_kernel<<<64, 256>>>(W_u1, W_u2);
    build_edges_kernel<<<NN / 8, 256>>>(adj, dist);
    in_proj_kernel<<<NN / 4, 128>>>(x, W_in, b_in);
    for (int s = 0; s < 3; s++) {
        msg_kernel<<<NN, 128>>>();
        update_tc_kernel<<<NN / 16, 256>>>(b_u1, b_u2, gamma, beta,
                                           (s == 2) ? out : h_ptr);
    }
}

// round 17
// speedup vs baseline: 1.1961x; 1.0388x over previous
#include <cuda_runtime.h>

#define NN   4096
#define HH   128
#define CAP  192   // max degree capacity; Binomial(4096,0.02) max ~= 127

// Scratch (device globals: allocation-free per harness rules)
__device__ float4 g_edge[NN * CAP];   // (j_bits, decay, wc, pad) per edge
__device__ int    g_deg[NN];
__device__ float  g_h[NN * HH];
__device__ float  g_m[NN * HH];
__device__ uint2  g_W1p[32 * 4 * 128];   // paired tf32 W1: [ks][tig][n] -> (k, k+4)
__device__ uint2  g_W2p[16 * 4 * 128];   // paired tf32 W2

// ---- packed fp32x2 helpers (Blackwell FFMA2) ----
__device__ __forceinline__ unsigned long long fma2(
    unsigned long long a, unsigned long long b, unsigned long long c)
{
    unsigned long long d;
    asm("fma.rn.f32x2 %0, %1, %2, %3;" : "=l"(d) : "l"(a), "l"(b), "l"(c));
    return d;
}
__device__ __forceinline__ unsigned long long packdup(float w)
{
    unsigned long long d;
    asm("mov.b64 %0, {%1, %1};" : "=l"(d) : "f"(w));
    return d;
}
__device__ __forceinline__ void unpack2(unsigned long long v, float& lo, float& hi)
{
    asm("mov.b64 {%0, %1}, %2;" : "=f"(lo), "=f"(hi) : "l"(v));
}
// ---- tf32 helpers ----
__device__ __forceinline__ unsigned f2tf32(float f)
{
    unsigned r;
    asm("cvt.rna.tf32.f32 %0, %1;" : "=r"(r) : "f"(f));
    return r;
}
__device__ __forceinline__ void mma_tf32(float* C,
    unsigned a0, unsigned a1, unsigned a2, unsigned a3,
    unsigned b0, unsigned b1)
{
    asm("mma.sync.aligned.m16n8k8.row.col.f32.tf32.tf32.f32 "
        "{%0,%1,%2,%3}, {%4,%5,%6,%7}, {%8,%9}, {%0,%1,%2,%3};"
        : "+f"(C[0]), "+f"(C[1]), "+f"(C[2]), "+f"(C[3])
        : "r"(a0), "r"(a1), "r"(a2), "r"(a3), "r"(b0), "r"(b1));
}

// ---------------------------------------------------------------------------
// Pack W1/W2 into tf32 pairs: g_Wp[(ks*4+tig)*128 + n] = (W[ks*8+tig][n],
// W[ks*8+tig+4][n]) so one LDG.64 yields a full mma B-fragment.
// ---------------------------------------------------------------------------
__global__ void prep_w_kernel(const float* __restrict__ W1,
                              const float* __restrict__ W2)
{
    int i = blockIdx.x * 256 + threadIdx.x;   // 0 .. 16383
    if (i < 32 * 4 * 128) {
        int n = i & 127, t = (i >> 7) & 3, ks = i >> 9;
        g_W1p[i] = make_uint2(f2tf32(W1[(ks * 8 + t) * 128 + n]),
                              f2tf32(W1[(ks * 8 + t + 4) * 128 + n]));
    }
    if (i < 16 * 4 * 128) {
        int n = i & 127, t = (i >> 7) & 3, ks = i >> 9;
        g_W2p[i] = make_uint2(f2tf32(W2[(ks * 8 + t) * 128 + n]),
                              f2tf32(W2[(ks * 8 + t + 4) * 128 + n]));
    }
}

// ---------------------------------------------------------------------------
// Build per-row edge list from adj (2% dense) with loop-invariant weights.
// ---------------------------------------------------------------------------
__global__ __launch_bounds__(256) void build_edges_kernel(
    const float* __restrict__ adj, const float* __restrict__ dist)
{
    int row  = blockIdx.x * 8 + (threadIdx.x >> 5);
    int lane = threadIdx.x & 31;
    if (row >= NN) return;
    const float4* arowv = (const float4*)(adj + (long)row * NN);  // 1024 float4
    const float*  drow  = dist + (long)row * NN;
    unsigned lt = (1u << lane) - 1u;
    int base = 0;
    for (int it = 0; it < 1024; it += 64) {
        float4 a = arowv[it + lane];
        float4 b = arowv[it + 32 + lane];
        unsigned m0 = __ballot_sync(0xffffffffu, a.x != 0.0f);
        unsigned m1 = __ballot_sync(0xffffffffu, a.y != 0.0f);
        unsigned m2 = __ballot_sync(0xffffffffu, a.z != 0.0f);
        unsigned m3 = __ballot_sync(0xffffffffu, a.w != 0.0f);
        unsigned n0 = __ballot_sync(0xffffffffu, b.x != 0.0f);
        unsigned n1 = __ballot_sync(0xffffffffu, b.y != 0.0f);
        unsigned n2 = __ballot_sync(0xffffffffu, b.z != 0.0f);
        unsigned n3 = __ballot_sync(0xffffffffu, b.w != 0.0f);
#pragma unroll
        for (int q = 0; q < 8; q++) {
            unsigned mask;
            float av;
            int col;
            switch (q) {
                case 0: mask = m0; av = a.x; col = (it + lane) * 4 + 0; break;
                case 1: mask = m1; av = a.y; col = (it + lane) * 4 + 1; break;
                case 2: mask = m2; av = a.z; col = (it + lane) * 4 + 2; break;
                case 3: mask = m3; av = a.w; col = (it + lane) * 4 + 3; break;
                case 4: mask = n0; av = b.x; col = (it + 32 + lane) * 4 + 0; break;
                case 5: mask = n1; av = b.y; col = (it + 32 + lane) * 4 + 1; break;
                case 6: mask = n2; av = b.z; col = (it + 32 + lane) * 4 + 2; break;
                default: mask = n3; av = b.w; col = (it + 32 + lane) * 4 + 3; break;
            }
            if (av != 0.0f) {
                int pos = base + __popc(mask & lt);
                if (pos < CAP) {
                    float d     = drow[col];
                    float decay = __expf(d * (-1.0f / 3.0f));
                    float r     = fmaxf(d, 1e-6f);
                    float inv   = 3.5f / r;
                    float i2    = inv * inv;
                    float i6    = i2 * i2 * i2;
                    float wc    = 0.04f * (i6 * i6 - i6);
                    g_edge[row * CAP + pos] =
                        make_float4(__int_as_float(col), decay, wc, 0.0f);
                }
            }
            base += __popc(mask);
        }
    }
    if (lane == 0) g_deg[row] = (base < CAP) ? base : CAP;
}

// ---------------------------------------------------------------------------
// h = x @ W_in + b_in  (4096x64 @ 64x128); 4 rows/block, grid 1024.
// ---------------------------------------------------------------------------
__global__ __launch_bounds__(128) void in_proj_kernel(
    const float* __restrict__ x, const float* __restrict__ W,
    const float* __restrict__ b)
{
    __shared__ __align__(16) float s_xT[64 * 4];   // [k][r]
    int c  = threadIdx.x;
    int r0 = blockIdx.x * 4;
    for (int i = threadIdx.x; i < 4 * 64; i += 128) {
        int r = i >> 6, k = i & 63;
        s_xT[k * 4 + r] = x[(long)(r0 + r) * 64 + k];
    }
    __syncthreads();

    typedef unsigned long long u64;
    u64 p01 = 0ull, p23 = 0ull;
    const float* wcol = W + c;
#pragma unroll 8
    for (int k = 0; k < 64; k++) {
        u64 ww = packdup(wcol[k * HH]);
        ulonglong2 av = *(const ulonglong2*)&s_xT[k * 4];
        p01 = fma2(av.x, ww, p01);
        p23 = fma2(av.y, ww, p23);
    }
    float h0, h1, h2, h3;
    unpack2(p01, h0, h1);
    unpack2(p23, h2, h3);
    float bias = b[c];
    g_h[(long)(r0 + 0) * HH + c] = h0 + bias;
    g_h[(long)(r0 + 1) * HH + c] = h1 + bias;
    g_h[(long)(r0 + 2) * HH + c] = h2 + bias;
    g_h[(long)(r0 + 3) * HH + c] = h3 + bias;
}

// ---------------------------------------------------------------------------
// m_i = sum_{j in N(i)} (decay_ij * relu(<h_i, h_j>) + wc_ij) * h_j
// One block (4 warps) per row. Edge metas are staged into smem first
// (coalesced burst, high MLP), so the per-batch dependent chain is only
// LDS(j) -> LDG(h_j) instead of LDG(meta) -> LDG(h_j).
// ---------------------------------------------------------------------------
__global__ __launch_bounds__(128) void msg_kernel()
{
    __shared__ float  s_hi[HH];
    __shared__ __align__(16) float4 s_em[CAP];
    __shared__ float  s_m[4 * HH];
    int row  = blockIdx.x;
    int tid  = threadIdx.x;
    int wid  = tid >> 5;
    int lane = tid & 31;
    int deg  = g_deg[row];

    s_hi[tid] = g_h[(long)row * HH + tid];
    for (int e = tid; e < deg; e += 128)
        s_em[e] = g_edge[row * CAP + e];
    __syncthreads();
    float4 hi4 = *(const float4*)&s_hi[lane * 4];

    float4 acc = make_float4(0.f, 0.f, 0.f, 0.f);

    for (int e0 = wid * 4; e0 < deg; e0 += 16) {
        float4 em[4], hj[4];
#pragma unroll
        for (int q = 0; q < 4; q++) {
            bool v = (e0 + q) < deg;
            em[q] = v ? s_em[e0 + q] : make_float4(0.f, 0.f, 0.f, 0.f);
            int j = v ? __float_as_int(em[q].x) : 0;
            hj[q] = *(const float4*)&g_h[(long)j * HH + lane * 4];
        }
        float d[4];
#pragma unroll
        for (int q = 0; q < 4; q++)
            d[q] = hi4.x * hj[q].x + hi4.y * hj[q].y
                 + hi4.z * hj[q].z + hi4.w * hj[q].w;
#pragma unroll
        for (int o = 16; o > 0; o >>= 1) {
#pragma unroll
            for (int q = 0; q < 4; q++)
                d[q] += __shfl_xor_sync(0xffffffffu, d[q], o);
        }
#pragma unroll
        for (int q = 0; q < 4; q++) {
            float cf = fmaf(em[q].y, fmaxf(d[q], 0.0f), em[q].z);  // 0 if invalid
            acc.x = fmaf(cf, hj[q].x, acc.x);
            acc.y = fmaf(cf, hj[q].y, acc.y);
            acc.z = fmaf(cf, hj[q].z, acc.z);
            acc.w = fmaf(cf, hj[q].w, acc.w);
        }
    }
    *(float4*)&s_m[wid * HH + lane * 4] = acc;
    __syncthreads();
    g_m[(long)row * HH + tid] =
        s_m[tid] + s_m[HH + tid] + s_m[2 * HH + tid] + s_m[3 * HH + tid];
}

// ---------------------------------------------------------------------------
// Tensor-core update: t = relu([h|m]@W1+b1); delta = t@W2+b2; out = LN(h+delta)
// 16 rows/block, 256 threads (8 warps), grid 256.
// mma.sync m16n8k8 tf32. Warp = (khalf = w>>2, nslice = (w&3)*32).
// khalf=1 partials reduced into khalf=0 via smem (exact fp32 adds).
// Residual + LN in exact fp32 (activations kept fp32 in smem; cvt at A-load).
// ---------------------------------------------------------------------------
__global__ __launch_bounds__(256) void update_tc_kernel(
    const float* __restrict__ b1, const float* __restrict__ b2,
    const float* __restrict__ gamma, const float* __restrict__ beta,
    float* __restrict__ out)
{
    __shared__ float s_cat[16][260];      // fp32 [row][k]: k<128 h, k>=128 m
    __shared__ float s_t[16][132];        // fp32 relu output
    __shared__ float s_red[4][32][16];    // khalf=1 fragment spills
    __shared__ float s_y[16][132];        // pre-LN rows
    int tid    = threadIdx.x;
    int warp   = tid >> 5;
    int lane   = tid & 31;
    int g      = lane >> 2;     // 0..7
    int tig    = lane & 3;      // 0..3
    int khalf  = warp >> 2;     // 0/1
    int wq     = warp & 3;      // n-slice index
    int nslice = wq * 32;
    int r0     = blockIdx.x * 16;

    for (int i = tid; i < 16 * 128; i += 256) {
        int r = i >> 7, k = i & 127;
        s_cat[r][k]       = g_h[(long)(r0 + r) * HH + k];
        s_cat[r][128 + k] = g_m[(long)(r0 + r) * HH + k];
    }
    __syncthreads();

    // ---- mlp1: C += cat @ W1 over this warp's k-half ----
    float C[4][4];
#pragma unroll
    for (int nt = 0; nt < 4; nt++)
#pragma unroll
        for (int j = 0; j < 4; j++) C[nt][j] = 0.0f;

    for (int ks = 0; ks < 16; ks++) {
        int ksg = khalf * 16 + ks;
        int k0  = ksg * 8;
        unsigned a0 = f2tf32(s_cat[g][k0 + tig]);
        unsigned a1 = f2tf32(s_cat[g + 8][k0 + tig]);
        unsigned a2 = f2tf32(s_cat[g][k0 + tig + 4]);
        unsigned a3 = f2tf32(s_cat[g + 8][k0 + tig + 4]);
        const uint2* wp = g_W1p + (ksg * 4 + tig) * 128 + nslice + g;
#pragma unroll
        for (int nt = 0; nt < 4; nt++) {
            uint2 b = wp[nt * 8];
            mma_tf32(C[nt], a0, a1, a2, a3, b.x, b.y);
        }
    }
    if (khalf == 1) {
        float4* dst = (float4*)&s_red[wq][lane][0];
#pragma unroll
        for (int nt = 0; nt < 4; nt++)
            dst[nt] = make_float4(C[nt][0], C[nt][1], C[nt][2], C[nt][3]);
    }
    __syncthreads();
    if (khalf == 0) {
        const float* sp = &s_red[wq][lane][0];
#pragma unroll
        for (int nt = 0; nt < 4; nt++) {
            int colb = nslice + nt * 8 + 2 * tig;
            float bi0 = b1[colb], bi1 = b1[colb + 1];
            s_t[g][colb]         = fmaxf(C[nt][0] + sp[nt * 4 + 0] + bi0, 0.0f);
            s_t[g][colb + 1]     = fmaxf(C[nt][1] + sp[nt * 4 + 1] + bi1, 0.0f);
            s_t[g + 8][colb]     = fmaxf(C[nt][2] + sp[nt * 4 + 2] + bi0, 0.0f);
            s_t[g + 8][colb + 1] = fmaxf(C[nt][3] + sp[nt * 4 + 3] + bi1, 0.0f);
        }
    }
    __syncthreads();

    // ---- mlp2: D += t @ W2 over this warp's k-half ----
#pragma unroll
    for (int nt = 0; nt < 4; nt++)
#pragma unroll
        for (int j = 0; j < 4; j++) C[nt][j] = 0.0f;

    for (int ks = 0; ks < 8; ks++) {
        int ksg = khalf * 8 + ks;
        int k0  = ksg * 8;
        unsigned a0 = f2tf32(s_t[g][k0 + tig]);
        unsigned a1 = f2tf32(s_t[g + 8][k0 + tig]);
        unsigned a2 = f2tf32(s_t[g][k0 + tig + 4]);
        unsigned a3 = f2tf32(s_t[g + 8][k0 + tig + 4]);
        const uint2* wp = g_W2p + (ksg * 4 + tig) * 128 + nslice + g;
#pragma unroll
        for (int nt = 0; nt < 4; nt++) {
            uint2 b = wp[nt * 8];
            mma_tf32(C[nt], a0, a1, a2, a3, b.x, b.y);
        }
    }
    if (khalf == 1) {
        float4* dst = (float4*)&s_red[wq][lane][0];
#pragma unroll
        for (int nt = 0; nt < 4; nt++)
            dst[nt] = make_float4(C[nt][0], C[nt][1], C[nt][2], C[nt][3]);
    }
    __syncthreads();
    if (khalf == 0) {
        const float* sp = &s_red[wq][lane][0];
#pragma unroll
        for (int nt = 0; nt < 4; nt++) {
            int colb = nslice + nt * 8 + 2 * tig;
            float bi0 = b2[colb], bi1 = b2[colb + 1];
            s_y[g][colb]         = s_cat[g][colb]         + C[nt][0] + sp[nt * 4 + 0] + bi0;
            s_y[g][colb + 1]     = s_cat[g][colb + 1]     + C[nt][1] + sp[nt * 4 + 1] + bi1;
            s_y[g + 8][colb]     = s_cat[g + 8][colb]     + C[nt][2] + sp[nt * 4 + 2] + bi0;
            s_y[g + 8][colb + 1] = s_cat[g + 8][colb + 1] + C[nt][3] + sp[nt * 4 + 3] + bi1;
        }
    }
    __syncthreads();

    // ---- layernorm: warp w handles rows w and w+8 ----
    float4 gm = *(const float4*)&gamma[lane * 4];
    float4 bt = *(const float4*)&beta[lane * 4];
#pragma unroll
    for (int rr = 0; rr < 2; rr++) {
        int r = warp + rr * 8;
        float4 yv = *(const float4*)&s_y[r][lane * 4];
        float s = yv.x + yv.y + yv.z + yv.w;
#pragma unroll
        for (int o = 16; o > 0; o >>= 1)
            s += __shfl_xor_sync(0xffffffffu, s, o);
        float mu = s * (1.0f / 128.0f);
        float dx = yv.x - mu, dy = yv.y - mu, dz = yv.z - mu, dw = yv.w - mu;
        float sq = dx * dx + dy * dy + dz * dz + dw * dw;
#pragma unroll
        for (int o = 16; o > 0; o >>= 1)
            sq += __shfl_xor_sync(0xffffffffu, sq, o);
        float rs = rsqrtf(sq * (1.0f / 128.0f) + 1e-5f);
        float4 o4;
        o4.x = dx * rs * gm.x + bt.x;
        o4.y = dy * rs * gm.y + bt.y;
        o4.z = dz * rs * gm.z + bt.z;
        o4.w = dw * rs * gm.w + bt.w;
        *(float4*)&out[(long)(r0 + r) * HH + lane * 4] = o4;
    }
}

// ---------------------------------------------------------------------------
extern "C" void kernel_launch(void* const* d_in, const int* in_sizes, int n_in,
                              void* d_out, int out_size)
{
    const float* x     = (const float*)d_in[0];
    const float* adj   = (const float*)d_in[1];
    const float* dist  = (const float*)d_in[2];
    const float* W_in  = (const float*)d_in[3];
    const float* b_in  = (const float*)d_in[4];
    // d_in[5] = W_msg, d_in[6] = b_msg : dead code in the reference
    const float* W_u1  = (const float*)d_in[7];
    const float* b_u1  = (const float*)d_in[8];
    const float* W_u2  = (const float*)d_in[9];
    const float* b_u2  = (const float*)d_in[10];
    const float* gamma = (const float*)d_in[11];
    const float* beta  = (const float*)d_in[12];
    float* out = (float*)d_out;

    float* h_ptr = nullptr;
    cudaGetSymbolAddress((void**)&h_ptr, g_h);

    prep_w_kernel<<<64, 256>>>(W_u1, W_u2);
    build_edges_kernel<<<NN / 8, 256>>>(adj, dist);
    in_proj_kernel<<<NN / 4, 128>>>(x, W_in, b_in);
    for (int s = 0; s < 3; s++) {
        msg_kernel<<<NN, 128>>>();
        update_tc_kernel<<<NN / 16, 256>>>(b_u1, b_u2, gamma, beta,
                                           (s == 2) ? out : h_ptr);
    }
}